// round 2
// baseline (speedup 1.0000x reference)
#include <cuda_runtime.h>
#include <cuda_bf16.h>

#define NN 100000
#define NE 1600000
#define FH 128
#define CC 64

// ---------------- scratch (static device allocations; no cudaMalloc) ----------------
__device__ float g_h[3ll * NN * FH];   // h1,h2,h3
__device__ float g_y[(long long)NN * FH];
__device__ float g_z[(long long)NN * CC];
__device__ float g_onorm[NN];
__device__ float g_inorm[NN];
__device__ int   g_indeg[NN];
__device__ int   g_outdeg[NN];
__device__ int   g_rs[NN + 1];         // CSR row starts (by dst)
__device__ int   g_cur[NN];
__device__ int   g_perm[NE];           // src node id, grouped by dst

// ---------------- graph prep ----------------
__global__ void k_degree(const int* __restrict__ src, const int* __restrict__ dst) {
    int e = blockIdx.x * blockDim.x + threadIdx.x;
    if (e < NE) {
        atomicAdd(&g_outdeg[src[e]], 1);
        atomicAdd(&g_indeg[dst[e]], 1);
    }
}

__global__ void k_norms() {
    int i = blockIdx.x * blockDim.x + threadIdx.x;
    if (i < NN) {
        int od = g_outdeg[i], id = g_indeg[i];
        g_onorm[i] = od > 0 ? rsqrtf((float)od) : 0.f;
        g_inorm[i] = id > 0 ? rsqrtf((float)id) : 0.f;
    }
}

// single-block exclusive scan of g_indeg -> g_rs, also inits g_cur
__global__ __launch_bounds__(1024) void k_scan() {
    __shared__ int sums[1024];
    int tid = threadIdx.x;
    const int chunk = (NN + 1023) / 1024;   // 98
    int b = tid * chunk;
    int e = min(b + chunk, NN);
    int s = 0;
    for (int i = b; i < e; i++) s += g_indeg[i];
    sums[tid] = s;
    __syncthreads();
    for (int off = 1; off < 1024; off <<= 1) {
        int v = (tid >= off) ? sums[tid - off] : 0;
        __syncthreads();
        sums[tid] += v;
        __syncthreads();
    }
    int run = (tid == 0) ? 0 : sums[tid - 1];
    for (int i = b; i < e; i++) {
        g_rs[i] = run;
        g_cur[i] = run;
        run += g_indeg[i];
    }
    if (tid == 1023) g_rs[NN] = run;
}

__global__ void k_build(const int* __restrict__ src, const int* __restrict__ dst) {
    int e = blockIdx.x * blockDim.x + threadIdx.x;
    if (e < NE) {
        int p = atomicAdd(&g_cur[dst[e]], 1);
        g_perm[p] = src[e];
    }
}

// ---------------- GEMM: Y[N,128] = (X .* onorm) @ W[128,128] ----------------
__global__ __launch_bounds__(256) void k_gemm_conv(const float* __restrict__ X,
                                                   const float* __restrict__ W,
                                                   float* __restrict__ Y) {
    __shared__ float As[32][65];    // [k][m], padded vs bank conflicts
    __shared__ float Bs[32][128];   // [k][n]
    int tid = threadIdx.x;
    int tx = tid & 15;              // 16 col-groups
    int ty = tid >> 4;              // 16 row-groups
    int row0 = blockIdx.x * 64;

    float acc[4][8];
#pragma unroll
    for (int i = 0; i < 4; i++)
#pragma unroll
        for (int j = 0; j < 8; j++) acc[i][j] = 0.f;

    for (int k0 = 0; k0 < 128; k0 += 32) {
#pragma unroll
        for (int i = tid; i < 64 * 32; i += 256) {
            int m = i >> 5, k = i & 31;
            int r = row0 + m;
            As[k][m] = (r < NN) ? X[r * 128 + k0 + k] * g_onorm[r] : 0.f;
        }
#pragma unroll
        for (int i = tid; i < 32 * 128; i += 256) {
            int k = i >> 7, c = i & 127;
            Bs[k][c] = W[(k0 + k) * 128 + c];
        }
        __syncthreads();
#pragma unroll
        for (int k = 0; k < 32; k++) {
            float a0 = As[k][ty * 4 + 0];
            float a1 = As[k][ty * 4 + 1];
            float a2 = As[k][ty * 4 + 2];
            float a3 = As[k][ty * 4 + 3];
            float4 b0 = *(const float4*)&Bs[k][tx * 4];
            float4 b1 = *(const float4*)&Bs[k][64 + tx * 4];
            acc[0][0] += a0 * b0.x; acc[0][1] += a0 * b0.y; acc[0][2] += a0 * b0.z; acc[0][3] += a0 * b0.w;
            acc[0][4] += a0 * b1.x; acc[0][5] += a0 * b1.y; acc[0][6] += a0 * b1.z; acc[0][7] += a0 * b1.w;
            acc[1][0] += a1 * b0.x; acc[1][1] += a1 * b0.y; acc[1][2] += a1 * b0.z; acc[1][3] += a1 * b0.w;
            acc[1][4] += a1 * b1.x; acc[1][5] += a1 * b1.y; acc[1][6] += a1 * b1.z; acc[1][7] += a1 * b1.w;
            acc[2][0] += a2 * b0.x; acc[2][1] += a2 * b0.y; acc[2][2] += a2 * b0.z; acc[2][3] += a2 * b0.w;
            acc[2][4] += a2 * b1.x; acc[2][5] += a2 * b1.y; acc[2][6] += a2 * b1.z; acc[2][7] += a2 * b1.w;
            acc[3][0] += a3 * b0.x; acc[3][1] += a3 * b0.y; acc[3][2] += a3 * b0.z; acc[3][3] += a3 * b0.w;
            acc[3][4] += a3 * b1.x; acc[3][5] += a3 * b1.y; acc[3][6] += a3 * b1.z; acc[3][7] += a3 * b1.w;
        }
        __syncthreads();
    }

#pragma unroll
    for (int i = 0; i < 4; i++) {
        int r = row0 + ty * 4 + i;
        if (r < NN) {
            float4 v0 = make_float4(acc[i][0], acc[i][1], acc[i][2], acc[i][3]);
            float4 v1 = make_float4(acc[i][4], acc[i][5], acc[i][6], acc[i][7]);
            *(float4*)&Y[r * 128 + tx * 4] = v0;
            *(float4*)&Y[r * 128 + 64 + tx * 4] = v1;
        }
    }
}

// ---------------- GEMM: Z[N,64] = concat(h1,h2,h3) @ Wo[384,64] ----------------
__global__ __launch_bounds__(256) void k_gemm_z(const float* __restrict__ Hc,
                                                 const float* __restrict__ Wo,
                                                 float* __restrict__ Z) {
    __shared__ float As[32][65];
    __shared__ float Bs[32][64];
    int tid = threadIdx.x;
    int tx = tid & 15;
    int ty = tid >> 4;
    int row0 = blockIdx.x * 64;

    float acc[4][4];
#pragma unroll
    for (int i = 0; i < 4; i++)
#pragma unroll
        for (int j = 0; j < 4; j++) acc[i][j] = 0.f;

    for (int k0 = 0; k0 < 384; k0 += 32) {
        int layer = k0 >> 7;
        int cb = k0 & 127;
        const float* Xb = Hc + (long long)layer * NN * 128;
#pragma unroll
        for (int i = tid; i < 64 * 32; i += 256) {
            int m = i >> 5, k = i & 31;
            int r = row0 + m;
            As[k][m] = (r < NN) ? Xb[r * 128 + cb + k] : 0.f;
        }
#pragma unroll
        for (int i = tid; i < 32 * 64; i += 256) {
            int k = i >> 6, c = i & 63;
            Bs[k][c] = Wo[(k0 + k) * 64 + c];
        }
        __syncthreads();
#pragma unroll
        for (int k = 0; k < 32; k++) {
            float a0 = As[k][ty * 4 + 0];
            float a1 = As[k][ty * 4 + 1];
            float a2 = As[k][ty * 4 + 2];
            float a3 = As[k][ty * 4 + 3];
            float4 b = *(const float4*)&Bs[k][tx * 4];
            acc[0][0] += a0 * b.x; acc[0][1] += a0 * b.y; acc[0][2] += a0 * b.z; acc[0][3] += a0 * b.w;
            acc[1][0] += a1 * b.x; acc[1][1] += a1 * b.y; acc[1][2] += a1 * b.z; acc[1][3] += a1 * b.w;
            acc[2][0] += a2 * b.x; acc[2][1] += a2 * b.y; acc[2][2] += a2 * b.z; acc[2][3] += a2 * b.w;
            acc[3][0] += a3 * b.x; acc[3][1] += a3 * b.y; acc[3][2] += a3 * b.z; acc[3][3] += a3 * b.w;
        }
        __syncthreads();
    }

#pragma unroll
    for (int i = 0; i < 4; i++) {
        int r = row0 + ty * 4 + i;
        if (r < NN) {
            float4 v = make_float4(acc[i][0], acc[i][1], acc[i][2], acc[i][3]);
            *(float4*)&Z[r * 64 + tx * 4] = v;
        }
    }
}

// ---------------- aggregation: h[v] = relu(inorm[v] * sum_{e:dst=v} y[src[e]] + b) ----------------
__global__ __launch_bounds__(128) void k_agg(const float* __restrict__ Y,
                                             const float* __restrict__ b,
                                             float* __restrict__ Hout) {
    int v = blockIdx.x;
    int t = threadIdx.x;
    int s = g_rs[v], e = g_rs[v + 1];
    float a0 = 0.f, a1 = 0.f, a2 = 0.f, a3 = 0.f;
    int j = s;
    for (; j + 4 <= e; j += 4) {
        int s0 = g_perm[j], s1 = g_perm[j + 1], s2 = g_perm[j + 2], s3 = g_perm[j + 3];
        a0 += __ldg(&Y[s0 * 128 + t]);
        a1 += __ldg(&Y[s1 * 128 + t]);
        a2 += __ldg(&Y[s2 * 128 + t]);
        a3 += __ldg(&Y[s3 * 128 + t]);
    }
    for (; j < e; j++) a0 += __ldg(&Y[g_perm[j] * 128 + t]);
    float r = ((a0 + a1) + (a2 + a3)) * g_inorm[v] + b[t];
    Hout[v * 128 + t] = fmaxf(r, 0.f);
}

// ---------------- final: out[v] = sum_{e:dst=v} z[src[e]] + bo ; 2 nodes per block ----------------
__global__ __launch_bounds__(128) void k_final(const float* __restrict__ bo,
                                               float* __restrict__ Out) {
    int v = blockIdx.x * 2 + (threadIdx.x >> 6);
    if (v >= NN) return;
    int t = threadIdx.x & 63;
    int s = g_rs[v], e = g_rs[v + 1];
    float a0 = 0.f, a1 = 0.f, a2 = 0.f, a3 = 0.f;
    int j = s;
    for (; j + 4 <= e; j += 4) {
        int s0 = g_perm[j], s1 = g_perm[j + 1], s2 = g_perm[j + 2], s3 = g_perm[j + 3];
        a0 += __ldg(&g_z[s0 * 64 + t]);
        a1 += __ldg(&g_z[s1 * 64 + t]);
        a2 += __ldg(&g_z[s2 * 64 + t]);
        a3 += __ldg(&g_z[s3 * 64 + t]);
    }
    for (; j < e; j++) a0 += __ldg(&g_z[g_perm[j] * 64 + t]);
    Out[v * 64 + t] = ((a0 + a1) + (a2 + a3)) + bo[t];
}

// ---------------- host ----------------
extern "C" void kernel_launch(void* const* d_in, const int* in_sizes, int n_in,
                              void* d_out, int out_size) {
    const float* feats = (const float*)d_in[0];
    const int*   src   = (const int*)d_in[1];
    const int*   dst   = (const int*)d_in[2];
    const float* W0    = (const float*)d_in[3];
    const float* b0    = (const float*)d_in[4];
    const float* W1    = (const float*)d_in[5];
    const float* b1    = (const float*)d_in[6];
    const float* W2    = (const float*)d_in[7];
    const float* b2    = (const float*)d_in[8];
    const float* Wo    = (const float*)d_in[9];
    const float* bo    = (const float*)d_in[10];
    float* out = (float*)d_out;

    void *p_indeg, *p_outdeg, *p_h, *p_y, *p_z;
    cudaGetSymbolAddress(&p_indeg, g_indeg);
    cudaGetSymbolAddress(&p_outdeg, g_outdeg);
    cudaGetSymbolAddress(&p_h, g_h);
    cudaGetSymbolAddress(&p_y, g_y);
    cudaGetSymbolAddress(&p_z, g_z);
    float* hbuf = (float*)p_h;
    float* ybuf = (float*)p_y;
    float* zbuf = (float*)p_z;

    cudaMemsetAsync(p_indeg, 0, NN * sizeof(int));
    cudaMemsetAsync(p_outdeg, 0, NN * sizeof(int));

    int eb = (NE + 255) / 256;
    k_degree<<<eb, 256>>>(src, dst);
    k_norms<<<(NN + 255) / 256, 256>>>();
    k_scan<<<1, 1024>>>();
    k_build<<<eb, 256>>>(src, dst);

    int gb = (NN + 63) / 64;
    // layer 1
    k_gemm_conv<<<gb, 256>>>(feats, W0, ybuf);
    k_agg<<<NN, 128>>>(ybuf, b0, hbuf);
    // layer 2
    k_gemm_conv<<<gb, 256>>>(hbuf, W1, ybuf);
    k_agg<<<NN, 128>>>(ybuf, b1, hbuf + (long long)NN * 128);
    // layer 3
    k_gemm_conv<<<gb, 256>>>(hbuf + (long long)NN * 128, W2, ybuf);
    k_agg<<<NN, 128>>>(ybuf, b2, hbuf + 2ll * NN * 128);
    // output projection BEFORE pooling (linearity): z = jk @ Wo, [N,64]
    k_gemm_z<<<gb, 256>>>(hbuf, Wo, zbuf);
    // pooled @ Wo + bo  ==  segsum(z[src]) + bo
    k_final<<<(NN + 1) / 2, 128>>>(bo, out);
}

// round 4
// speedup vs baseline: 1.6177x; 1.6177x over previous
#include <cuda_runtime.h>
#include <cuda_bf16.h>
#include <cstdint>

#define NN 100000
#define NE 1600000
#define FH 128
#define CC 64

// ---------------- scratch ----------------
__device__ float g_h[3ll * NN * FH];   // h1,h2,h3
__device__ float g_y[(long long)NN * FH];
__device__ float g_z[(long long)NN * CC];
__device__ float g_onorm[NN];
__device__ float g_inorm[NN];
__device__ int   g_indeg[NN];
__device__ int   g_outdeg[NN];
__device__ int   g_rs[NN + 1];
__device__ int   g_cur[NN];
__device__ int   g_perm[NE];

// ---------------- helpers ----------------
__device__ __forceinline__ uint32_t to_tf32(float x) {
    uint32_t y;
    asm("cvt.rna.tf32.f32 %0, %1;" : "=r"(y) : "f"(x));
    return y;
}
__device__ __forceinline__ float to_tf32f(float x) {
    return __uint_as_float(to_tf32(x));
}

__device__ __forceinline__ void mma_tf32(float* c, const uint32_t* a, uint32_t b0, uint32_t b1) {
    asm volatile(
        "mma.sync.aligned.m16n8k8.row.col.f32.tf32.tf32.f32 "
        "{%0,%1,%2,%3}, {%4,%5,%6,%7}, {%8,%9}, {%0,%1,%2,%3};"
        : "+f"(c[0]), "+f"(c[1]), "+f"(c[2]), "+f"(c[3])
        : "r"(a[0]), "r"(a[1]), "r"(a[2]), "r"(a[3]), "r"(b0), "r"(b1));
}

// ---------------- graph prep ----------------
__global__ void k_degree(const int* __restrict__ src, const int* __restrict__ dst) {
    int e = blockIdx.x * blockDim.x + threadIdx.x;
    if (e < NE) {
        atomicAdd(&g_outdeg[src[e]], 1);
        atomicAdd(&g_indeg[dst[e]], 1);
    }
}

__global__ void k_norms() {
    int i = blockIdx.x * blockDim.x + threadIdx.x;
    if (i < NN) {
        int od = g_outdeg[i], id = g_indeg[i];
        g_onorm[i] = od > 0 ? rsqrtf((float)od) : 0.f;
        g_inorm[i] = id > 0 ? rsqrtf((float)id) : 0.f;
    }
}

__global__ __launch_bounds__(1024) void k_scan() {
    __shared__ int sums[1024];
    int tid = threadIdx.x;
    const int chunk = (NN + 1023) / 1024;
    int b = tid * chunk;
    int e = min(b + chunk, NN);
    int s = 0;
    for (int i = b; i < e; i++) s += g_indeg[i];
    sums[tid] = s;
    __syncthreads();
    for (int off = 1; off < 1024; off <<= 1) {
        int v = (tid >= off) ? sums[tid - off] : 0;
        __syncthreads();
        sums[tid] += v;
        __syncthreads();
    }
    int run = (tid == 0) ? 0 : sums[tid - 1];
    for (int i = b; i < e; i++) {
        g_rs[i] = run;
        g_cur[i] = run;
        run += g_indeg[i];
    }
    if (tid == 1023) g_rs[NN] = run;
}

__global__ void k_build(const int* __restrict__ src, const int* __restrict__ dst) {
    int e = blockIdx.x * blockDim.x + threadIdx.x;
    if (e < NE) {
        int p = atomicAdd(&g_cur[dst[e]], 1);
        g_perm[p] = src[e];
    }
}

// ---------------- TF32 GEMM: Y[N,128] = (X .* onorm) @ W[128,128] ----------------
// block: 256 thr (8 warps), tile M=128, N=128 full. warp w -> rows [w*16, w*16+16).
__global__ __launch_bounds__(256) void k_gemm_conv_tc(const float* __restrict__ X,
                                                      const float* __restrict__ W,
                                                      float* __restrict__ Y) {
    __shared__ float As[128][36];   // [m][k], stride%32=4 -> frag loads conflict-free
    __shared__ float Ws[32][136];   // [k][n], stride%32=8 -> frag loads conflict-free
    int tid = threadIdx.x;
    int warp = tid >> 5, lane = tid & 31;
    int gid = lane >> 2, tig = lane & 3;
    int row0 = blockIdx.x * 128;

    float acc[16][4];
#pragma unroll
    for (int i = 0; i < 16; i++)
#pragma unroll
        for (int j = 0; j < 4; j++) acc[i][j] = 0.f;

    for (int kc = 0; kc < 4; kc++) {
        int k0 = kc * 32;
        // stage A (convert to tf32, scale by onorm)
#pragma unroll
        for (int i = tid; i < 1024; i += 256) {
            int m = i >> 3, kq = (i & 7) * 4;
            int r = row0 + m;
            float4 v = make_float4(0.f, 0.f, 0.f, 0.f);
            float on = 0.f;
            if (r < NN) { v = *(const float4*)&X[r * 128 + k0 + kq]; on = g_onorm[r]; }
            As[m][kq + 0] = to_tf32f(v.x * on);
            As[m][kq + 1] = to_tf32f(v.y * on);
            As[m][kq + 2] = to_tf32f(v.z * on);
            As[m][kq + 3] = to_tf32f(v.w * on);
        }
        // stage W (row-major [k][n])
#pragma unroll
        for (int i = tid; i < 1024; i += 256) {
            int k = i >> 5, nq = (i & 31) * 4;
            float4 v = *(const float4*)&W[(k0 + k) * 128 + nq];
            Ws[k][nq + 0] = to_tf32f(v.x);
            Ws[k][nq + 1] = to_tf32f(v.y);
            Ws[k][nq + 2] = to_tf32f(v.z);
            Ws[k][nq + 3] = to_tf32f(v.w);
        }
        __syncthreads();
#pragma unroll
        for (int ks = 0; ks < 4; ks++) {
            int kk = ks * 8;
            uint32_t a[4];
            a[0] = __float_as_uint(As[warp * 16 + gid][kk + tig]);
            a[1] = __float_as_uint(As[warp * 16 + gid + 8][kk + tig]);
            a[2] = __float_as_uint(As[warp * 16 + gid][kk + tig + 4]);
            a[3] = __float_as_uint(As[warp * 16 + gid + 8][kk + tig + 4]);
#pragma unroll
            for (int nt = 0; nt < 16; nt++) {
                uint32_t b0 = __float_as_uint(Ws[kk + tig][nt * 8 + gid]);
                uint32_t b1 = __float_as_uint(Ws[kk + tig + 4][nt * 8 + gid]);
                mma_tf32(acc[nt], a, b0, b1);
            }
        }
        __syncthreads();
    }

    int r0 = row0 + warp * 16 + gid;
    int r1 = r0 + 8;
#pragma unroll
    for (int nt = 0; nt < 16; nt++) {
        int c = nt * 8 + tig * 2;
        if (r0 < NN) *(float2*)&Y[r0 * 128 + c] = make_float2(acc[nt][0], acc[nt][1]);
        if (r1 < NN) *(float2*)&Y[r1 * 128 + c] = make_float2(acc[nt][2], acc[nt][3]);
    }
}

// ---------------- TF32 GEMM: Z[N,64] = concat(h1,h2,h3) @ Wo[384,64] ----------------
__global__ __launch_bounds__(256) void k_gemm_z_tc(const float* __restrict__ Hc,
                                                   const float* __restrict__ Wo,
                                                   float* __restrict__ Z) {
    __shared__ float As[128][36];
    __shared__ float Ws[32][72];    // stride%32=8
    int tid = threadIdx.x;
    int warp = tid >> 5, lane = tid & 31;
    int gid = lane >> 2, tig = lane & 3;
    int row0 = blockIdx.x * 128;

    float acc[8][4];
#pragma unroll
    for (int i = 0; i < 8; i++)
#pragma unroll
        for (int j = 0; j < 4; j++) acc[i][j] = 0.f;

    for (int kc = 0; kc < 12; kc++) {
        int k0 = kc * 32;
        int layer = k0 >> 7;
        int cb = k0 & 127;
        const float* Xb = Hc + (long long)layer * NN * 128;
#pragma unroll
        for (int i = tid; i < 1024; i += 256) {
            int m = i >> 3, kq = (i & 7) * 4;
            int r = row0 + m;
            float4 v = make_float4(0.f, 0.f, 0.f, 0.f);
            if (r < NN) v = *(const float4*)&Xb[r * 128 + cb + kq];
            As[m][kq + 0] = to_tf32f(v.x);
            As[m][kq + 1] = to_tf32f(v.y);
            As[m][kq + 2] = to_tf32f(v.z);
            As[m][kq + 3] = to_tf32f(v.w);
        }
#pragma unroll
        for (int i = tid; i < 512; i += 256) {
            int k = i >> 4, nq = (i & 15) * 4;
            float4 v = *(const float4*)&Wo[(k0 + k) * 64 + nq];
            Ws[k][nq + 0] = to_tf32f(v.x);
            Ws[k][nq + 1] = to_tf32f(v.y);
            Ws[k][nq + 2] = to_tf32f(v.z);
            Ws[k][nq + 3] = to_tf32f(v.w);
        }
        __syncthreads();
#pragma unroll
        for (int ks = 0; ks < 4; ks++) {
            int kk = ks * 8;
            uint32_t a[4];
            a[0] = __float_as_uint(As[warp * 16 + gid][kk + tig]);
            a[1] = __float_as_uint(As[warp * 16 + gid + 8][kk + tig]);
            a[2] = __float_as_uint(As[warp * 16 + gid][kk + tig + 4]);
            a[3] = __float_as_uint(As[warp * 16 + gid + 8][kk + tig + 4]);
#pragma unroll
            for (int nt = 0; nt < 8; nt++) {
                uint32_t b0 = __float_as_uint(Ws[kk + tig][nt * 8 + gid]);
                uint32_t b1 = __float_as_uint(Ws[kk + tig + 4][nt * 8 + gid]);
                mma_tf32(acc[nt], a, b0, b1);
            }
        }
        __syncthreads();
    }

    int r0 = row0 + warp * 16 + gid;
    int r1 = r0 + 8;
#pragma unroll
    for (int nt = 0; nt < 8; nt++) {
        int c = nt * 8 + tig * 2;
        if (r0 < NN) *(float2*)&Z[r0 * 64 + c] = make_float2(acc[nt][0], acc[nt][1]);
        if (r1 < NN) *(float2*)&Z[r1 * 64 + c] = make_float2(acc[nt][2], acc[nt][3]);
    }
}

// ---------------- aggregation: warp per node, float4 lanes ----------------
__global__ __launch_bounds__(256) void k_agg(const float* __restrict__ Y,
                                             const float* __restrict__ b,
                                             float* __restrict__ Hout) {
    int v = (blockIdx.x * 256 + threadIdx.x) >> 5;
    if (v >= NN) return;
    int lane = threadIdx.x & 31;
    int col = lane * 4;
    int s = g_rs[v], e = g_rs[v + 1];
    float4 a0 = make_float4(0.f, 0.f, 0.f, 0.f), a1 = a0, a2 = a0, a3 = a0;
    int j = s;
    for (; j + 4 <= e; j += 4) {
        int s0 = __ldg(&g_perm[j]), s1 = __ldg(&g_perm[j + 1]);
        int s2 = __ldg(&g_perm[j + 2]), s3 = __ldg(&g_perm[j + 3]);
        float4 v0 = __ldg((const float4*)&Y[s0 * 128 + col]);
        float4 v1 = __ldg((const float4*)&Y[s1 * 128 + col]);
        float4 v2 = __ldg((const float4*)&Y[s2 * 128 + col]);
        float4 v3 = __ldg((const float4*)&Y[s3 * 128 + col]);
        a0.x += v0.x; a0.y += v0.y; a0.z += v0.z; a0.w += v0.w;
        a1.x += v1.x; a1.y += v1.y; a1.z += v1.z; a1.w += v1.w;
        a2.x += v2.x; a2.y += v2.y; a2.z += v2.z; a2.w += v2.w;
        a3.x += v3.x; a3.y += v3.y; a3.z += v3.z; a3.w += v3.w;
    }
    for (; j < e; j++) {
        float4 v0 = __ldg((const float4*)&Y[__ldg(&g_perm[j]) * 128 + col]);
        a0.x += v0.x; a0.y += v0.y; a0.z += v0.z; a0.w += v0.w;
    }
    float in = g_inorm[v];
    float4 bb = __ldg((const float4*)&b[col]);
    float4 r;
    r.x = fmaxf((a0.x + a1.x + a2.x + a3.x) * in + bb.x, 0.f);
    r.y = fmaxf((a0.y + a1.y + a2.y + a3.y) * in + bb.y, 0.f);
    r.z = fmaxf((a0.z + a1.z + a2.z + a3.z) * in + bb.z, 0.f);
    r.w = fmaxf((a0.w + a1.w + a2.w + a3.w) * in + bb.w, 0.f);
    *(float4*)&Hout[v * 128 + col] = r;
}

// ---------------- final: warp per node, float2 lanes ----------------
__global__ __launch_bounds__(256) void k_final(const float* __restrict__ bo,
                                               float* __restrict__ Out) {
    int v = (blockIdx.x * 256 + threadIdx.x) >> 5;
    if (v >= NN) return;
    int lane = threadIdx.x & 31;
    int col = lane * 2;
    int s = g_rs[v], e = g_rs[v + 1];
    float2 a0 = make_float2(0.f, 0.f), a1 = a0, a2 = a0, a3 = a0;
    int j = s;
    for (; j + 4 <= e; j += 4) {
        int s0 = __ldg(&g_perm[j]), s1 = __ldg(&g_perm[j + 1]);
        int s2 = __ldg(&g_perm[j + 2]), s3 = __ldg(&g_perm[j + 3]);
        float2 v0 = __ldg((const float2*)&g_z[s0 * 64 + col]);
        float2 v1 = __ldg((const float2*)&g_z[s1 * 64 + col]);
        float2 v2 = __ldg((const float2*)&g_z[s2 * 64 + col]);
        float2 v3 = __ldg((const float2*)&g_z[s3 * 64 + col]);
        a0.x += v0.x; a0.y += v0.y;
        a1.x += v1.x; a1.y += v1.y;
        a2.x += v2.x; a2.y += v2.y;
        a3.x += v3.x; a3.y += v3.y;
    }
    for (; j < e; j++) {
        float2 v0 = __ldg((const float2*)&g_z[__ldg(&g_perm[j]) * 64 + col]);
        a0.x += v0.x; a0.y += v0.y;
    }
    float2 bb = __ldg((const float2*)&bo[col]);
    Out[v * 64 + col + 0] = (a0.x + a1.x) + (a2.x + a3.x) + bb.x;
    Out[v * 64 + col + 1] = (a0.y + a1.y) + (a2.y + a3.y) + bb.y;
}

// ---------------- host ----------------
extern "C" void kernel_launch(void* const* d_in, const int* in_sizes, int n_in,
                              void* d_out, int out_size) {
    const float* feats = (const float*)d_in[0];
    const int*   src   = (const int*)d_in[1];
    const int*   dst   = (const int*)d_in[2];
    const float* W0    = (const float*)d_in[3];
    const float* b0    = (const float*)d_in[4];
    const float* W1    = (const float*)d_in[5];
    const float* b1    = (const float*)d_in[6];
    const float* W2    = (const float*)d_in[7];
    const float* b2    = (const float*)d_in[8];
    const float* Wo    = (const float*)d_in[9];
    const float* bo    = (const float*)d_in[10];
    float* out = (float*)d_out;

    void *p_indeg, *p_outdeg, *p_h, *p_y, *p_z;
    cudaGetSymbolAddress(&p_indeg, g_indeg);
    cudaGetSymbolAddress(&p_outdeg, g_outdeg);
    cudaGetSymbolAddress(&p_h, g_h);
    cudaGetSymbolAddress(&p_y, g_y);
    cudaGetSymbolAddress(&p_z, g_z);
    float* hbuf = (float*)p_h;
    float* ybuf = (float*)p_y;
    float* zbuf = (float*)p_z;

    cudaMemsetAsync(p_indeg, 0, NN * sizeof(int));
    cudaMemsetAsync(p_outdeg, 0, NN * sizeof(int));

    int eb = (NE + 255) / 256;
    k_degree<<<eb, 256>>>(src, dst);
    k_norms<<<(NN + 255) / 256, 256>>>();
    k_scan<<<1, 1024>>>();
    k_build<<<eb, 256>>>(src, dst);

    int gb = (NN + 127) / 128;           // 782 blocks, tile M=128
    int ab = (NN * 32 + 255) / 256;      // warp per node

    k_gemm_conv_tc<<<gb, 256>>>(feats, W0, ybuf);
    k_agg<<<ab, 256>>>(ybuf, b0, hbuf);
    k_gemm_conv_tc<<<gb, 256>>>(hbuf, W1, ybuf);
    k_agg<<<ab, 256>>>(ybuf, b1, hbuf + (long long)NN * 128);
    k_gemm_conv_tc<<<gb, 256>>>(hbuf + (long long)NN * 128, W2, ybuf);
    k_agg<<<ab, 256>>>(ybuf, b2, hbuf + 2ll * NN * 128);
    k_gemm_z_tc<<<gb, 256>>>(hbuf, Wo, zbuf);
    k_final<<<ab, 256>>>(bo, out);
}